// round 9
// baseline (speedup 1.0000x reference)
#include <cuda_runtime.h>
#include <math.h>

// One block = 256x1 output strip, one thread = 1 pixel x 3 channels.
// Matrix: lane 0 of each warp computes, shfl-broadcast (NO block barrier).
// Strip-level OOB interval test -> float4 zero fast path for ~75% of blocks.
// Closed form: overall = fw^-1 * diag(1/l1,1/l2,1) * fw; translation = 0.
__global__ __launch_bounds__(256)
void warp_kernel(const float* __restrict__ x, float* __restrict__ out,
                 const float* __restrict__ thetas,
                 const float* __restrict__ l1s,
                 const float* __restrict__ l2s,
                 int H, int W) {
    const int b = blockIdx.z;
    const int h = blockIdx.y;
    const int w_start = blockIdx.x * 256;
    const int tid = threadIdx.x;
    const int lane = tid & 31;

    float A00, A01, A11;
    if (lane == 0) {
        float c, s;
        __sincosf(thetas[b], &s, &c);
        float i1 = 1.0f / l1s[b];
        float i2 = 1.0f / l2s[b];
        A00 = c * c * i1 + s * s * i2;
        A01 = c * s * (i1 - i2);
        A11 = s * s * i1 + c * c * i2;
    }
    A00 = __shfl_sync(0xffffffffu, A00, 0);
    A01 = __shfl_sync(0xffffffffu, A01, 0);
    A11 = __shfl_sync(0xffffffffu, A11, 0);

    const int HW = H * W;
    const float fW = (float)W, fH = (float)H;
    const float yn = ((float)h + 0.5f) * (2.0f / fH) - 1.0f;

    // --- strip-level interval test (gx, gy monotone linear along the strip) ---
    bool full_strip = (w_start + 255 < W);
    if (full_strip) {
        float xnL = ((float)w_start + 0.5f) * (2.0f / fW) - 1.0f;
        float xnR = ((float)(w_start + 255) + 0.5f) * (2.0f / fW) - 1.0f;
        float gxL = (A00 * xnL + A01 * yn + 1.0f) * (fW * 0.5f) - 0.5f;
        float gxR = (A00 * xnR + A01 * yn + 1.0f) * (fW * 0.5f) - 0.5f;
        float gyL = (A01 * xnL + A11 * yn + 1.0f) * (fH * 0.5f) - 0.5f;
        float gyR = (A01 * xnR + A11 * yn + 1.0f) * (fH * 0.5f) - 0.5f;
        float gxmin = fminf(gxL, gxR), gxmax = fmaxf(gxL, gxR);
        float gymin = fminf(gyL, gyR), gymax = fmaxf(gyL, gyR);
        // +0.5px slack vs the per-pixel test to absorb fp-contraction differences
        bool hit = (gxmax > -1.5f) && (gxmin < fW + 0.5f) &&
                   (gymax > -1.5f) && (gymin < fH + 0.5f);
        if (!hit) {
            // whole strip is zero: 192 threads store one float4 each (3ch x 64)
            float* op0 = out + (long long)(b * 3) * HW + h * W + w_start;
            if (tid < 192) {
                int c = tid >> 6;        // channel 0..2
                int i = tid & 63;        // float4 index within strip
                ((float4*)(op0 + c * HW))[i] = make_float4(0.f, 0.f, 0.f, 0.f);
            }
            return;
        }
    }

    // --- per-pixel path ---
    const int w = w_start + tid;
    if (w >= W) return;

    float xn = ((float)w + 0.5f) * (2.0f / fW) - 1.0f;
    float gx = (A00 * xn + A01 * yn + 1.0f) * (fW * 0.5f) - 0.5f;
    float gy = (A01 * xn + A11 * yn + 1.0f) * (fH * 0.5f) - 0.5f;

    float* op = out + (long long)(b * 3) * HW + h * W + w;

    if (!(gx > -1.0f) || gx >= fW || !(gy > -1.0f) || gy >= fH) {
        op[0] = 0.0f;
        op[HW] = 0.0f;
        op[2 * HW] = 0.0f;
        return;
    }

    float x0f = floorf(gx), y0f = floorf(gy);
    int x0 = (int)x0f, y0 = (int)y0f;
    int x1 = x0 + 1, y1 = y0 + 1;
    float wx1 = gx - x0f, wx0 = 1.0f - wx1;
    float wy1 = gy - y0f, wy0 = 1.0f - wy1;

    // in-bounds guarantees from early-out: x0 < W, x1 >= 0, y0 < H, y1 >= 0
    float fx0 = (x0 >= 0) ? wx0 : 0.0f;
    float fx1 = (x1 < W) ? wx1 : 0.0f;
    float fy0 = (y0 >= 0) ? wy0 : 0.0f;
    float fy1 = (y1 < H) ? wy1 : 0.0f;

    int xc0 = max(x0, 0);
    int xc1 = min(x1, W - 1);
    int yc0 = max(y0, 0);
    int yc1 = min(y1, H - 1);

    int o00 = yc0 * W + xc0;
    int o01 = yc0 * W + xc1;
    int o10 = yc1 * W + xc0;
    int o11 = yc1 * W + xc1;

    float w00 = fy0 * fx0, w01 = fy0 * fx1;
    float w10 = fy1 * fx0, w11 = fy1 * fx1;

    const float* p0 = x + (long long)(b * 3) * HW;
    const float* p1 = p0 + HW;
    const float* p2 = p1 + HW;

    // 12 independent gathers -> max MLP
    float v000 = __ldg(p0 + o00), v001 = __ldg(p0 + o01);
    float v010 = __ldg(p0 + o10), v011 = __ldg(p0 + o11);
    float v100 = __ldg(p1 + o00), v101 = __ldg(p1 + o01);
    float v110 = __ldg(p1 + o10), v111 = __ldg(p1 + o11);
    float v200 = __ldg(p2 + o00), v201 = __ldg(p2 + o01);
    float v210 = __ldg(p2 + o10), v211 = __ldg(p2 + o11);

    op[0]      = w00 * v000 + w01 * v001 + w10 * v010 + w11 * v011;
    op[HW]     = w00 * v100 + w01 * v101 + w10 * v110 + w11 * v111;
    op[2 * HW] = w00 * v200 + w01 * v201 + w10 * v210 + w11 * v211;
}

extern "C" void kernel_launch(void* const* d_in, const int* in_sizes, int n_in,
                              void* d_out, int out_size) {
    const float* x      = (const float*)d_in[0];
    const float* thetas = (const float*)d_in[1];
    const float* l1s    = (const float*)d_in[2];
    const float* l2s    = (const float*)d_in[3];
    float* out = (float*)d_out;

    int B = in_sizes[1];
    long long hw = (long long)in_sizes[0] / ((long long)B * 3);
    int W = (int)(sqrt((double)hw) + 0.5);
    int H = (int)(hw / W);

    dim3 block(256, 1, 1);
    dim3 grid((W + 255) / 256, H, B);
    warp_kernel<<<grid, block>>>(x, out, thetas, l1s, l2s, H, W);
}

// round 12
// speedup vs baseline: 1.1791x; 1.1791x over previous
#include <cuda_runtime.h>
#include <math.h>

// Per-batch affine coefficients: A00, A01, A11 (A10 = A01, translation = 0).
__device__ float4 g_A[256];

__global__ void mats_kernel(const float* __restrict__ thetas,
                            const float* __restrict__ l1s,
                            const float* __restrict__ l2s, int B) {
    int b = threadIdx.x;
    if (b < B) {
        float c, s;
        __sincosf(thetas[b], &s, &c);
        float i1 = 1.0f / l1s[b];
        float i2 = 1.0f / l2s[b];
        g_A[b] = make_float4(c * c * i1 + s * s * i2,
                             c * s * (i1 - i2),
                             s * s * i1 + c * c * i2, 0.0f);
    }
    __threadfence();
#if __CUDA_ARCH__ >= 900
    cudaTriggerProgrammaticLaunchCompletion();
#endif
}

// One thread = 1 output pixel x 3 channels; 256x1 row strips (R1 hot path).
__global__ __launch_bounds__(256)
void warp_kernel(const float* __restrict__ x, float* __restrict__ out,
                 int H, int W) {
#if __CUDA_ARCH__ >= 900
    cudaGridDependencySynchronize();
#endif
    const int b = blockIdx.z;
    const int h = blockIdx.y;
    const int w = blockIdx.x * 256 + threadIdx.x;
    if (w >= W) return;

    const float4 A = g_A[b];

    float xn = ((float)w + 0.5f) * (2.0f / (float)W) - 1.0f;
    float yn = ((float)h + 0.5f) * (2.0f / (float)H) - 1.0f;
    float gx = (A.x * xn + A.y * yn + 1.0f) * ((float)W * 0.5f) - 0.5f;
    float gy = (A.y * xn + A.z * yn + 1.0f) * ((float)H * 0.5f) - 0.5f;

    const int HW = H * W;
    float* op = out + (long long)(b * 3) * HW + h * W + w;

    if (!(gx > -1.0f) || gx >= (float)W || !(gy > -1.0f) || gy >= (float)H) {
        op[0] = 0.0f;
        op[HW] = 0.0f;
        op[2 * HW] = 0.0f;
        return;
    }

    float x0f = floorf(gx), y0f = floorf(gy);
    int x0 = (int)x0f, y0 = (int)y0f;
    int x1 = x0 + 1, y1 = y0 + 1;
    float wx1 = gx - x0f, wx0 = 1.0f - wx1;
    float wy1 = gy - y0f, wy0 = 1.0f - wy1;

    // in-bounds guarantees from early-out: x0 < W, x1 >= 0, y0 < H, y1 >= 0
    float fx0 = (x0 >= 0) ? wx0 : 0.0f;
    float fx1 = (x1 < W) ? wx1 : 0.0f;
    float fy0 = (y0 >= 0) ? wy0 : 0.0f;
    float fy1 = (y1 < H) ? wy1 : 0.0f;

    int xc0 = max(x0, 0);
    int xc1 = min(x1, W - 1);
    int yc0 = max(y0, 0);
    int yc1 = min(y1, H - 1);

    int o00 = yc0 * W + xc0;
    int o01 = yc0 * W + xc1;
    int o10 = yc1 * W + xc0;
    int o11 = yc1 * W + xc1;

    float w00 = fy0 * fx0, w01 = fy0 * fx1;
    float w10 = fy1 * fx0, w11 = fy1 * fx1;

    const float* p0 = x + (long long)(b * 3) * HW;
    const float* p1 = p0 + HW;
    const float* p2 = p1 + HW;

    // 12 independent gathers -> max MLP
    float v000 = __ldg(p0 + o00), v001 = __ldg(p0 + o01);
    float v010 = __ldg(p0 + o10), v011 = __ldg(p0 + o11);
    float v100 = __ldg(p1 + o00), v101 = __ldg(p1 + o01);
    float v110 = __ldg(p1 + o10), v111 = __ldg(p1 + o11);
    float v200 = __ldg(p2 + o00), v201 = __ldg(p2 + o01);
    float v210 = __ldg(p2 + o10), v211 = __ldg(p2 + o11);

    op[0]      = w00 * v000 + w01 * v001 + w10 * v010 + w11 * v011;
    op[HW]     = w00 * v100 + w01 * v101 + w10 * v110 + w11 * v111;
    op[2 * HW] = w00 * v200 + w01 * v201 + w10 * v210 + w11 * v211;
}

extern "C" void kernel_launch(void* const* d_in, const int* in_sizes, int n_in,
                              void* d_out, int out_size) {
    const float* x      = (const float*)d_in[0];
    const float* thetas = (const float*)d_in[1];
    const float* l1s    = (const float*)d_in[2];
    const float* l2s    = (const float*)d_in[3];
    float* out = (float*)d_out;

    int B = in_sizes[1];
    long long hw = (long long)in_sizes[0] / ((long long)B * 3);
    int W = (int)(sqrt((double)hw) + 0.5);
    int H = (int)(hw / W);

    mats_kernel<<<1, 32>>>(thetas, l1s, l2s, B);

    dim3 block(256, 1, 1);
    dim3 grid((W + 255) / 256, H, B);

    // Programmatic dependent launch: overlap warp_kernel's launch/prologue
    // with mats_kernel; device-side cudaGridDependencySynchronize() orders
    // the g_A read. Fall back to a plain launch if the attribute fails.
    cudaLaunchConfig_t cfg = {};
    cfg.gridDim = grid;
    cfg.blockDim = block;
    cfg.dynamicSmemBytes = 0;
    cfg.stream = 0;
    cudaLaunchAttribute attr[1];
    attr[0].id = cudaLaunchAttributeProgrammaticStreamSerialization;
    attr[0].val.programmaticStreamSerializationAllowed = 1;
    cfg.attrs = attr;
    cfg.numAttrs = 1;

    cudaError_t err = cudaLaunchKernelEx(&cfg, warp_kernel, x, out, H, W);
    if (err != cudaSuccess) {
        warp_kernel<<<grid, block>>>(x, out, H, W);
    }
}